// round 6
// baseline (speedup 1.0000x reference)
#include <cuda_runtime.h>

#define B_ 64
#define T_ 1024
#define C_ 2
#define N_ 128

// ---- packed f32x2 helpers (Blackwell sm_100+) ----
__device__ __forceinline__ unsigned long long pk2(float lo, float hi) {
    unsigned long long r;
    asm("mov.b64 %0, {%1, %2};" : "=l"(r) : "f"(lo), "f"(hi));
    return r;
}
__device__ __forceinline__ void upk2(unsigned long long v, float& lo, float& hi) {
    asm("mov.b64 {%0, %1}, %2;" : "=f"(lo), "=f"(hi) : "l"(v));
}
__device__ __forceinline__ void fma2(unsigned long long& acc, unsigned long long a,
                                     unsigned long long b) {
    asm("fma.rn.f32x2 %0, %1, %2, %0;" : "+l"(acc) : "l"(a), "l"(b));
}
__device__ __forceinline__ unsigned long long add2(unsigned long long a,
                                                   unsigned long long b) {
    unsigned long long r;
    asm("add.rn.f32x2 %0, %1, %2;" : "=l"(r) : "l"(a), "l"(b));
    return r;
}

// Packed dot over ALL 128 rows: S_j = sum_i r_i * E_ij.
__device__ __forceinline__ float dot128(const float* rbuf,
                                        const unsigned long long* e2) {
    unsigned long long a0 = 0ull, a1 = 0ull, a2 = 0ull, a3 = 0ull;
    const ulonglong2* pv = reinterpret_cast<const ulonglong2*>(rbuf);
#pragma unroll
    for (int k = 0; k < 32; ++k) {       // 32 * 4 floats = 128 rows
        ulonglong2 v = pv[k];
        if ((k & 1) == 0) { fma2(a0, e2[2 * k], v.x); fma2(a1, e2[2 * k + 1], v.y); }
        else              { fma2(a2, e2[2 * k], v.x); fma2(a3, e2[2 * k + 1], v.y); }
    }
    a0 = add2(a0, a1);
    a2 = add2(a2, a3);
    a0 = add2(a0, a2);
    float lo, hi;
    upk2(a0, lo, hi);
    return lo + hi;
}

// One CTA = both C-chains of one batch element b (same len -> lockstep).
// Warps 0-3: chain c=0; warps 4-7: chain c=1. Each SMSP hosts one warp of
// each chain, so independent chains interleave and hide each other's
// barrier/LDS latency bubbles.
__global__ void __launch_bounds__(256, 1)
crf_fwd_kernel(const float* __restrict__ emissions,   // [B,T,C,N]
               const int*   __restrict__ lengths,     // [B]
               const float* __restrict__ trans,       // [1,C,N,N]
               const float* __restrict__ start_t,     // [1,C,N]
               const float* __restrict__ end_t,       // [1,C,N]
               float*       __restrict__ out)         // [B,C]
{
    const int tid = threadIdx.x;
    const int c   = tid >> 7;           // chain within CTA (0 or 1)
    const int j   = tid & 127;          // tag column this thread owns
    const int b   = blockIdx.x;
    const int wq  = (tid >> 5) & 3;     // warp-quarter within chain
    const int len = lengths[b];         // in [T/2, T], shared by both chains

    __shared__ __align__(16) float r_sh[2][C_][N_];   // [buf][chain][tag]
    __shared__ __align__(16) float red_sh[C_][4];

    // ---- E packed: e2[m] = (exp(trans[c,2m,j]), exp(trans[c,2m+1,j])) ----
    unsigned long long e2[64];
    {
        const float* tb = trans + (size_t)c * N_ * N_ + j;
#pragma unroll
        for (int m = 0; m < 64; ++m) {
            float lo = __expf(tb[(size_t)(2 * m) * N_]);
            float hi = __expf(tb[(size_t)(2 * m + 1) * N_]);
            e2[m] = pk2(lo, hi);
        }
    }

    const float* ebase = emissions + ((size_t)b * T_ * C_ + c) * N_ + j;
    const int estride = C_ * N_;

    // ---- init: r_0 = exp(start + emit_0), unnormalized ----
    r_sh[0][c][j] = __expf(start_t[c * N_ + j] + ebase[0]);
    float logK = 0.f;
    __syncthreads();

    // ---- RAW emission ring, depth 8; __expf applied only at consumption ----
    float ering[8];
#pragma unroll
    for (int d = 1; d <= 8; ++d) {
        int tt = d; tt = (tt > T_ - 1) ? (T_ - 1) : tt;
        ering[d & 7] = __ldg(ebase + (size_t)tt * estride);
    }

    // ---- main scan: steps t = 1 .. len-1, early exit (len uniform per CTA) ----
    int t = 1;
#pragma unroll 1
    for (; t + 7 < len; t += 8) {       // t stays ≡ 1 (mod 8)
#pragma unroll
        for (int u = 0; u < 8; ++u) {
            const int cur  = (1 + u) & 1;   // compile-time buffer parity
            const int prv  = cur ^ 1;
            const int slot = (1 + u) & 7;   // compile-time ring slot
            const int tq   = t + u;

            // uniform normalizer from previous step (broadcast LDS)
            float cn  = r_sh[prv][c][0];
            float inv = __fdividef(1.0f, cn);
            logK += __logf(cn);             // off critical path

            // emission: exp of an 8-step-old raw value; refill 8 ahead (raw)
            float em = __expf(ering[slot]);
            int tt = tq + 8; tt = (tt > T_ - 1) ? (T_ - 1) : tt;
            ering[slot] = __ldg(ebase + (size_t)tt * estride);

            float S = dot128(r_sh[prv][c], e2);
            r_sh[cur][c][j] = S * (em * inv);
            __syncthreads();
        }
    }
    // tail (≤ 7 steps), runtime parity
#pragma unroll 1
    for (; t < len; ++t) {
        const int cur = t & 1;
        const int prv = cur ^ 1;
        float cn  = r_sh[prv][c][0];
        float inv = __fdividef(1.0f, cn);
        logK += __logf(cn);
        float em = __expf(ering[t & 7]);
        int tt = t + 8; tt = (tt > T_ - 1) ? (T_ - 1) : tt;
        ering[t & 7] = __ldg(ebase + (size_t)tt * estride);
        float S = dot128(r_sh[prv][c], e2);
        r_sh[cur][c][j] = S * (em * inv);
        __syncthreads();
    }

    // ---- finalize: logZ = logK + log( sum_j r_j * exp(end_j) ) ----
    float v = r_sh[(len - 1) & 1][c][j] * __expf(end_t[c * N_ + j]);
    float s = v;
#pragma unroll
    for (int o = 16; o > 0; o >>= 1)
        s += __shfl_xor_sync(0xffffffffu, s, o);
    if ((j & 31) == 0) red_sh[c][wq] = s;
    __syncthreads();
    if (j == 0) {
        float Sf = (red_sh[c][0] + red_sh[c][1]) + (red_sh[c][2] + red_sh[c][3]);
        out[b * C_ + c] = logK + logf(Sf);
    }
}

extern "C" void kernel_launch(void* const* d_in, const int* in_sizes, int n_in,
                              void* d_out, int out_size) {
    // Identify inputs by element count (robust to metadata ordering).
    const float* emissions = nullptr;
    const int*   lengths   = nullptr;
    const float* trans     = nullptr;
    const float* start_t   = nullptr;
    const float* end_t     = nullptr;

    for (int i = 0; i < n_in; ++i) {
        int sz = in_sizes[i];
        if (sz == B_ * T_ * C_ * N_)      emissions = (const float*)d_in[i];
        else if (sz == B_)                lengths   = (const int*)d_in[i];
        else if (sz == C_ * N_ * N_)      trans     = (const float*)d_in[i];
    }
    if (n_in > 3 && in_sizes[3] == C_ * N_) start_t = (const float*)d_in[3];
    for (int i = 0; i < n_in; ++i) {
        if (in_sizes[i] == C_ * N_ && (const float*)d_in[i] != start_t)
            end_t = (const float*)d_in[i];
    }
    if (!start_t) {
        for (int i = 0; i < n_in; ++i)
            if (in_sizes[i] == C_ * N_) { start_t = (const float*)d_in[i]; break; }
        for (int i = 0; i < n_in; ++i)
            if (in_sizes[i] == C_ * N_ && (const float*)d_in[i] != start_t)
                end_t = (const float*)d_in[i];
    }

    float* out = (float*)d_out;
    crf_fwd_kernel<<<B_, 256>>>(emissions, lengths, trans, start_t, end_t, out);
}

// round 7
// speedup vs baseline: 1.0513x; 1.0513x over previous
#include <cuda_runtime.h>

#define B_ 64
#define T_ 1024
#define C_ 2
#define N_ 128

// Named split-barrier (producer/consumer on barrier 1; count = 2 * 128 threads:
// each thread contributes one bar.arrive and one bar.sync arrival per phase).
#define BAR1_ARRIVE() asm volatile("bar.arrive 1, 256;" ::: "memory")
#define BAR1_SYNC()   asm volatile("bar.sync 1, 256;"   ::: "memory")

// ---- packed f32x2 helpers (Blackwell sm_100+) ----
__device__ __forceinline__ unsigned long long pk2(float lo, float hi) {
    unsigned long long r;
    asm("mov.b64 %0, {%1, %2};" : "=l"(r) : "f"(lo), "f"(hi));
    return r;
}
__device__ __forceinline__ void upk2(unsigned long long v, float& lo, float& hi) {
    asm("mov.b64 {%0, %1}, %2;" : "=f"(lo), "=f"(hi) : "l"(v));
}
__device__ __forceinline__ void fma2(unsigned long long& acc, unsigned long long a,
                                     unsigned long long b) {
    asm("fma.rn.f32x2 %0, %1, %2, %0;" : "+l"(acc) : "l"(a), "l"(b));
}
__device__ __forceinline__ unsigned long long add2(unsigned long long a,
                                                   unsigned long long b) {
    unsigned long long r;
    asm("add.rn.f32x2 %0, %1, %2;" : "=l"(r) : "l"(a), "l"(b));
    return r;
}

// Packed dot over ALL 128 rows: S_j = sum_i r_i * E_ij. Also returns r[0] (cn).
__device__ __forceinline__ float dot128_cn(const float* rbuf,
                                           const unsigned long long* e2,
                                           float& cn) {
    const ulonglong2* pv = reinterpret_cast<const ulonglong2*>(rbuf);
    unsigned long long a0, a1, a2 = 0ull, a3 = 0ull;
    ulonglong2 v0 = pv[0];
    {
        float lo, hi;
        upk2(v0.x, lo, hi);
        cn = lo;                       // r[0], free: already loaded for the dot
    }
    a0 = 0ull; a1 = 0ull;
    fma2(a0, e2[0], v0.x);
    fma2(a1, e2[1], v0.y);
#pragma unroll
    for (int k = 1; k < 32; ++k) {     // 32 * 4 floats = 128 rows
        ulonglong2 v = pv[k];
        if ((k & 1) == 0) { fma2(a0, e2[2 * k], v.x); fma2(a1, e2[2 * k + 1], v.y); }
        else              { fma2(a2, e2[2 * k], v.x); fma2(a3, e2[2 * k + 1], v.y); }
    }
    a0 = add2(a0, a1);
    a2 = add2(a2, a3);
    a0 = add2(a0, a2);
    float lo, hi;
    upk2(a0, lo, hi);
    return lo + hi;
}

__global__ void __launch_bounds__(128, 1)
crf_fwd_kernel(const float* __restrict__ emissions,   // [B,T,C,N]
               const int*   __restrict__ lengths,     // [B]
               const float* __restrict__ trans,       // [1,C,N,N]
               const float* __restrict__ start_t,     // [1,C,N]
               const float* __restrict__ end_t,       // [1,C,N]
               float*       __restrict__ out)         // [B,C]
{
    const int j   = threadIdx.x;        // tag column this thread owns
    const int bc  = blockIdx.x;         // chain id
    const int b   = bc >> 1;
    const int c   = bc & 1;
    const int wid = j >> 5;
    const int len = lengths[b];         // in [T/2, T]

    __shared__ __align__(16) float r_sh[2][N_];
    __shared__ __align__(16) float red_sh[4];

    // ---- E packed: e2[m] = (exp(trans[c,2m,j]), exp(trans[c,2m+1,j])) ----
    unsigned long long e2[64];
    {
        const float* tb = trans + (size_t)c * N_ * N_ + j;
#pragma unroll
        for (int m = 0; m < 64; ++m) {
            float lo = __expf(tb[(size_t)(2 * m) * N_]);
            float hi = __expf(tb[(size_t)(2 * m + 1) * N_]);
            e2[m] = pk2(lo, hi);
        }
    }

    const float* ebase = emissions + ((size_t)b * T_ * C_ + c) * N_ + j;
    const int estride = C_ * N_;

    // ---- init: r_0 = exp(start + emit_0), unnormalized ----
    r_sh[0][j] = __expf(start_t[c * N_ + j] + ebase[0]);
    float logK = 0.f;

    // ---- RAW emission ring, depth 8; slot (t & 7) holds raw emit_t ----
    float ering[8];
#pragma unroll
    for (int d = 1; d <= 8; ++d) {
        int tt = d; tt = (tt > T_ - 1) ? (T_ - 1) : tt;
        ering[d & 7] = __ldg(ebase + (size_t)tt * estride);
    }
    // em pipelined one step ahead: entering step t, em == exp(emit_t)
    float em = __expf(ering[1]);
    __syncthreads();

    // ---- main scan: steps t = 1 .. len-1 (len uniform per CTA) ----
    // Growth control: r drifts ~e^{+5.3}/step; normalizing every 4th step keeps
    // magnitudes <= ~e^45, far inside fp32 range. Exactness preserved via logK.
    int t = 1;
#pragma unroll 1
    for (; t + 7 < len; t += 8) {       // t stays ≡ 1 (mod 8)
#pragma unroll
        for (int u = 0; u < 8; ++u) {
            const int  cur  = (1 + u) & 1;     // compile-time buffer parity
            const int  prv  = cur ^ 1;
            const bool norm = ((u & 3) == 3);  // normalize at u = 3, 7
            const int  snxt = (u + 2) & 7;     // ring slot of step t+u+1

            // ---- critical path: LDS -> dot -> mul -> STS ----
            float cn;
            float S = dot128_cn(r_sh[prv], e2, cn);
            float rnew;
            if (norm) {
                float inv = __fdividef(1.0f, cn);  // runs concurrent w/ dot
                logK += __logf(cn);
                rnew = S * (em * inv);
            } else {
                rnew = S * em;
            }
            r_sh[cur][j] = rnew;
            BAR1_ARRIVE();

            // ---- shadow work (hidden under other warps' arrival skew) ----
            em = __expf(ering[snxt]);          // em for step t+u+1
            int tp = t + u + 9;                // refill slot snxt with t+u+9
            tp = (tp > T_ - 1) ? (T_ - 1) : tp;
            ering[snxt] = __ldg(ebase + (size_t)tp * estride);

            BAR1_SYNC();
        }
    }
    // tail (≤ 7 steps): normalize every step, plain barriers
#pragma unroll 1
    for (; t < len; ++t) {
        const int cur = t & 1;
        const int prv = cur ^ 1;
        float cn;
        float S = dot128_cn(r_sh[prv], e2, cn);
        float inv = __fdividef(1.0f, cn);
        logK += __logf(cn);
        r_sh[cur][j] = S * (em * inv);
        em = __expf(ering[(t + 1) & 7]);       // ring holds t+1..t+8: valid
        __syncthreads();
    }

    __syncthreads();

    // ---- finalize: logZ = logK + log( sum_j r_j * exp(end_j) ) ----
    float v = r_sh[(len - 1) & 1][j] * __expf(end_t[c * N_ + j]);
    float s = v;
#pragma unroll
    for (int o = 16; o > 0; o >>= 1)
        s += __shfl_xor_sync(0xffffffffu, s, o);
    if ((j & 31) == 0) red_sh[wid] = s;
    __syncthreads();
    if (j == 0) {
        float Sf = (red_sh[0] + red_sh[1]) + (red_sh[2] + red_sh[3]);
        out[bc] = logK + logf(Sf);
    }
}

extern "C" void kernel_launch(void* const* d_in, const int* in_sizes, int n_in,
                              void* d_out, int out_size) {
    // Identify inputs by element count (robust to metadata ordering).
    const float* emissions = nullptr;
    const int*   lengths   = nullptr;
    const float* trans     = nullptr;
    const float* start_t   = nullptr;
    const float* end_t     = nullptr;

    for (int i = 0; i < n_in; ++i) {
        int sz = in_sizes[i];
        if (sz == B_ * T_ * C_ * N_)      emissions = (const float*)d_in[i];
        else if (sz == B_)                lengths   = (const int*)d_in[i];
        else if (sz == C_ * N_ * N_)      trans     = (const float*)d_in[i];
    }
    if (n_in > 3 && in_sizes[3] == C_ * N_) start_t = (const float*)d_in[3];
    for (int i = 0; i < n_in; ++i) {
        if (in_sizes[i] == C_ * N_ && (const float*)d_in[i] != start_t)
            end_t = (const float*)d_in[i];
    }
    if (!start_t) {
        for (int i = 0; i < n_in; ++i)
            if (in_sizes[i] == C_ * N_) { start_t = (const float*)d_in[i]; break; }
        for (int i = 0; i < n_in; ++i)
            if (in_sizes[i] == C_ * N_ && (const float*)d_in[i] != start_t)
                end_t = (const float*)d_in[i];
    }

    float* out = (float*)d_out;
    crf_fwd_kernel<<<B_ * C_, N_>>>(emissions, lengths, trans, start_t, end_t, out);
}

// round 8
// speedup vs baseline: 1.6945x; 1.6118x over previous
#include <cuda_runtime.h>

#define B_ 64
#define T_ 1024
#define C_ 2
#define N_ 128

// ---- packed f32x2 helpers (Blackwell sm_100+) ----
__device__ __forceinline__ unsigned long long pk2(float lo, float hi) {
    unsigned long long r;
    asm("mov.b64 %0, {%1, %2};" : "=l"(r) : "f"(lo), "f"(hi));
    return r;
}
__device__ __forceinline__ void upk2(unsigned long long v, float& lo, float& hi) {
    asm("mov.b64 {%0, %1}, %2;" : "=f"(lo), "=f"(hi) : "l"(v));
}
__device__ __forceinline__ void fma2(unsigned long long& acc, unsigned long long a,
                                     unsigned long long b) {
    asm("fma.rn.f32x2 %0, %1, %2, %0;" : "+l"(acc) : "l"(a), "l"(b));
}
__device__ __forceinline__ unsigned long long add2(unsigned long long a,
                                                   unsigned long long b) {
    unsigned long long r;
    asm("add.rn.f32x2 %0, %1, %2;" : "=l"(r) : "l"(a), "l"(b));
    return r;
}

// Packed dot over ALL 128 rows: S_j = sum_i r_i * E_ij.
__device__ __forceinline__ float dot128(const float* rbuf,
                                        const unsigned long long* e2) {
    unsigned long long a0 = 0ull, a1 = 0ull, a2 = 0ull, a3 = 0ull;
    const ulonglong2* pv = reinterpret_cast<const ulonglong2*>(rbuf);
#pragma unroll
    for (int k = 0; k < 32; ++k) {       // 32 * 4 floats = 128 rows
        ulonglong2 v = pv[k];
        if ((k & 1) == 0) { fma2(a0, e2[2 * k], v.x); fma2(a1, e2[2 * k + 1], v.y); }
        else              { fma2(a2, e2[2 * k], v.x); fma2(a3, e2[2 * k + 1], v.y); }
    }
    a0 = add2(a0, a1);
    a2 = add2(a2, a3);
    a0 = add2(a0, a2);
    float lo, hi;
    upk2(a0, lo, hi);
    return lo + hi;
}

__global__ void __launch_bounds__(128, 1)
crf_fwd_kernel(const float* __restrict__ emissions,   // [B,T,C,N]
               const int*   __restrict__ lengths,     // [B]
               const float* __restrict__ trans,       // [1,C,N,N]
               const float* __restrict__ start_t,     // [1,C,N]
               const float* __restrict__ end_t,       // [1,C,N]
               float*       __restrict__ out)         // [B,C]
{
    const int j   = threadIdx.x;        // tag column this thread owns
    const int bc  = blockIdx.x;         // chain id
    const int b   = bc >> 1;
    const int c   = bc & 1;
    const int wid = j >> 5;
    const int len = lengths[b];         // in [T/2, T]

    __shared__ __align__(16) float r_sh[2][N_];
    __shared__ __align__(16) float red_sh[4];

    // ---- E packed: e2[m] = (exp(trans[c,2m,j]), exp(trans[c,2m+1,j])) ----
    unsigned long long e2[64];
    {
        const float* tb = trans + (size_t)c * N_ * N_ + j;
#pragma unroll
        for (int m = 0; m < 64; ++m) {
            float lo = __expf(tb[(size_t)(2 * m) * N_]);
            float hi = __expf(tb[(size_t)(2 * m + 1) * N_]);
            e2[m] = pk2(lo, hi);
        }
    }

    const float* ebase = emissions + ((size_t)b * T_ * C_ + c) * N_ + j;
    const int estride = C_ * N_;

    // ---- init: r_0 = exp(start + emit_0), unnormalized ----
    r_sh[0][j] = __expf(start_t[c * N_ + j] + ebase[0]);
    int kacc = 0;                       // sum of biased exponents (exact norm log)
    __syncthreads();

    // ---- RAW emission ring, depth 8; slot (t & 7) holds raw emit_t.
    //      __expf applied only at consumption (8 steps after the load). ----
    float ering[8];
#pragma unroll
    for (int d = 1; d <= 8; ++d) {
        int tt = d; tt = (tt > T_ - 1) ? (T_ - 1) : tt;
        ering[d & 7] = __ldg(ebase + (size_t)tt * estride);
    }

    // ---- main scan, clamp-free: refills reach t+15 <= len-1 <= T-1 ----
    int t = 1;
#pragma unroll 1
    for (; t + 15 < len; t += 8) {      // t stays ≡ 1 (mod 8)
#pragma unroll
        for (int u = 0; u < 8; ++u) {
            const int cur  = (1 + u) & 1;   // compile-time buffer parity
            const int prv  = cur ^ 1;
            const int slot = (1 + u) & 7;   // compile-time ring slot
            const int tq   = t + u;

            // power-of-2 normalizer from previous step's r[0] (broadcast LDS).
            // inv = 2^{-e} exactly; log contribution is the integer exponent.
            float cn = r_sh[prv][0];
            int   ke = (__float_as_int(cn) >> 23) & 0xff;
            float inv = __int_as_float((254 - ke) << 23);
            kacc += ke;

            // emission: exp of an 8-step-old raw value; refill 8 ahead (raw)
            float em = __expf(ering[slot]);
            ering[slot] = __ldg(ebase + (size_t)(tq + 8) * estride);

            float S = dot128(r_sh[prv], e2);
            r_sh[cur][j] = S * (em * inv);
            __syncthreads();
        }
    }
    // tail (≤ 15 steps), runtime parity, clamped refills
#pragma unroll 1
    for (; t < len; ++t) {
        const int cur = t & 1;
        const int prv = cur ^ 1;
        float cn = r_sh[prv][0];
        int   ke = (__float_as_int(cn) >> 23) & 0xff;
        float inv = __int_as_float((254 - ke) << 23);
        kacc += ke;
        float em = __expf(ering[t & 7]);
        int tt = t + 8; tt = (tt > T_ - 1) ? (T_ - 1) : tt;
        ering[t & 7] = __ldg(ebase + (size_t)tt * estride);
        float S = dot128(r_sh[prv], e2);
        r_sh[cur][j] = S * (em * inv);
        __syncthreads();
    }

    // ---- finalize: logZ = (kacc - 127*(len-1))*ln2 + log( sum_j r_j e^{end_j} ) ----
    float v = r_sh[(len - 1) & 1][j] * __expf(end_t[c * N_ + j]);
    float s = v;
#pragma unroll
    for (int o = 16; o > 0; o >>= 1)
        s += __shfl_xor_sync(0xffffffffu, s, o);
    if ((j & 31) == 0) red_sh[wid] = s;
    __syncthreads();
    if (j == 0) {
        float Sf = (red_sh[0] + red_sh[1]) + (red_sh[2] + red_sh[3]);
        float logK = (float)(kacc - 127 * (len - 1)) * 0.6931471805599453f;
        out[bc] = logK + logf(Sf);
    }
}

extern "C" void kernel_launch(void* const* d_in, const int* in_sizes, int n_in,
                              void* d_out, int out_size) {
    // Identify inputs by element count (robust to metadata ordering).
    const float* emissions = nullptr;
    const int*   lengths   = nullptr;
    const float* trans     = nullptr;
    const float* start_t   = nullptr;
    const float* end_t     = nullptr;

    for (int i = 0; i < n_in; ++i) {
        int sz = in_sizes[i];
        if (sz == B_ * T_ * C_ * N_)      emissions = (const float*)d_in[i];
        else if (sz == B_)                lengths   = (const int*)d_in[i];
        else if (sz == C_ * N_ * N_)      trans     = (const float*)d_in[i];
    }
    if (n_in > 3 && in_sizes[3] == C_ * N_) start_t = (const float*)d_in[3];
    for (int i = 0; i < n_in; ++i) {
        if (in_sizes[i] == C_ * N_ && (const float*)d_in[i] != start_t)
            end_t = (const float*)d_in[i];
    }
    if (!start_t) {
        for (int i = 0; i < n_in; ++i)
            if (in_sizes[i] == C_ * N_) { start_t = (const float*)d_in[i]; break; }
        for (int i = 0; i < n_in; ++i)
            if (in_sizes[i] == C_ * N_ && (const float*)d_in[i] != start_t)
                end_t = (const float*)d_in[i];
    }

    float* out = (float*)d_out;
    crf_fwd_kernel<<<B_ * C_, N_>>>(emissions, lengths, trans, start_t, end_t, out);
}